// round 12
// baseline (speedup 1.0000x reference)
#include <cuda_runtime.h>
#include <cuda_fp16.h>
#include <cstdint>

#define T_SEQ 2048
#define NHEADS 16
#define NEMB 1024
#define HD 64
#define BATCH 4

// ---------------------------------------------------------------------------
// Scratch (no allocation allowed anywhere) — half-precision pipeline
// ---------------------------------------------------------------------------
__device__ __half g_xh[(size_t)BATCH * T_SEQ * NEMB];
__device__ __half g_wqkvh[(size_t)NEMB * 3 * NEMB];
__device__ __half g_wouth[(size_t)NEMB * NEMB];
__device__ __half g_qkvh[(size_t)BATCH * T_SEQ * 3 * NEMB];
__device__ __half g_attnh[(size_t)BATCH * T_SEQ * NEMB];

// ---------------------------------------------------------------------------
// PTX helpers (baseline PTX only — sm_103 non-'a' target)
// ---------------------------------------------------------------------------
__device__ __forceinline__ uint32_t smem_to_u32(const void* p) {
    uint32_t a;
    asm("{ .reg .u64 t; cvta.to.shared.u64 t, %1; cvt.u32.u64 %0, t; }" : "=r"(a) : "l"(p));
    return a;
}
__device__ __forceinline__ void mma_f16(float* d, const uint32_t* a, const uint32_t* b) {
    asm volatile(
        "mma.sync.aligned.m16n8k16.row.col.f32.f16.f16.f32 "
        "{%0,%1,%2,%3}, {%4,%5,%6,%7}, {%8,%9}, {%0,%1,%2,%3};"
        : "+f"(d[0]), "+f"(d[1]), "+f"(d[2]), "+f"(d[3])
        : "r"(a[0]), "r"(a[1]), "r"(a[2]), "r"(a[3]), "r"(b[0]), "r"(b[1]));
}
#define LDSM_X4(r, addr) \
    asm volatile("ldmatrix.sync.aligned.m8n8.x4.shared.b16 {%0,%1,%2,%3}, [%4];" \
                 : "=r"((r)[0]), "=r"((r)[1]), "=r"((r)[2]), "=r"((r)[3]) : "r"(addr))
#define LDSM_X4T(r, addr) \
    asm volatile("ldmatrix.sync.aligned.m8n8.x4.trans.shared.b16 {%0,%1,%2,%3}, [%4];" \
                 : "=r"((r)[0]), "=r"((r)[1]), "=r"((r)[2]), "=r"((r)[3]) : "r"(addr))
#define CP_ASYNC16(dst, src) \
    asm volatile("cp.async.cg.shared.global [%0], [%1], 16;" :: "r"(dst), "l"(src))
#define CP_COMMIT()  asm volatile("cp.async.commit_group;" ::: "memory")
#define CP_WAIT1()   asm volatile("cp.async.wait_group 1;" ::: "memory")
#define CP_WAIT0()   asm volatile("cp.async.wait_group 0;" ::: "memory")

// ---------------------------------------------------------------------------
// fp32 -> fp16 elementwise convert (n % 4 == 0)
// ---------------------------------------------------------------------------
__global__ void f2h(const float* __restrict__ in, __half* __restrict__ out, int n) {
    int stride = gridDim.x * blockDim.x;
    for (int i = blockIdx.x * blockDim.x + threadIdx.x; i * 4 < n; i += stride) {
        float4 v = ((const float4*)in)[i];
        __half2* o = (__half2*)(out + (size_t)i * 4);
        o[0] = __floats2half2_rn(v.x, v.y);
        o[1] = __floats2half2_rn(v.z, v.w);
    }
}

// ---------------------------------------------------------------------------
// fp16 mma.sync GEMM v3 (unchanged from R11, measured 165.9us):
// CTA 128x128, 128 threads / 4 warps, warp tile 64x64, 2-stage cp.async.
// ---------------------------------------------------------------------------
#define HG_AST 10240                 // A stage bytes (128*40*2)
#define HG_BST 8704                  // B stage bytes (32*136*2)
#define HG_B_BASE (2 * HG_AST)
#define HG_SMEM_BYTES (2 * (HG_AST + HG_BST))   // 37888

__global__ __launch_bounds__(128) void hgemm(const __half* __restrict__ A,
                                             const __half* __restrict__ B,
                                             const float* __restrict__ bias,
                                             void* __restrict__ Cout,
                                             int M, int N, int K, int half_out) {
    extern __shared__ char smc[];
    const uint32_t sbase = smem_to_u32(smc);
    const int tid = threadIdx.x;
    const int wid = tid >> 5, lane = tid & 31;
    const int wm = wid & 1, wn = wid >> 1;
    const int lr = lane >> 2, kc = lane & 3;
    const int m0 = blockIdx.y * 128, n0 = blockIdx.x * 128;

    auto load_tile = [&](int c, int st) {
        const uint32_t asb = sbase + st * HG_AST;
        const uint32_t bsb = sbase + HG_B_BASE + st * HG_BST;
        const __half* Ac = A + (size_t)m0 * K + c * 32;
        const __half* Bc = B + (size_t)(c * 32) * N + n0;
#pragma unroll
        for (int i = 0; i < 4; i++) {
            int id = tid + i * 128;
            int am = id >> 2, ak = id & 3;
            CP_ASYNC16(asb + (uint32_t)(am * 40 + ak * 8) * 2,
                       Ac + (size_t)am * K + ak * 8);
            int bk = id >> 4, bn = id & 15;
            CP_ASYNC16(bsb + (uint32_t)(bk * 136 + bn * 8) * 2,
                       Bc + (size_t)bk * N + bn * 8);
        }
        CP_COMMIT();
    };

    float acc[4][8][4];
#pragma unroll
    for (int i = 0; i < 4; i++)
#pragma unroll
        for (int j = 0; j < 8; j++)
#pragma unroll
            for (int r = 0; r < 4; r++) acc[i][j][r] = 0.f;

    const int NT = K >> 5;
    load_tile(0, 0);

    const int mbase = wm * 64, nbase = wn * 64;
    const int a_row = (lane & 15);
    const int a_colh = (lane >> 4) * 8;

    for (int c = 0; c < NT; c++) {
        const int buf = c & 1;
        if (c + 1 < NT) { load_tile(c + 1, buf ^ 1); CP_WAIT1(); }
        else            { CP_WAIT0(); }
        __syncthreads();

        const uint32_t asb = sbase + buf * HG_AST;
        const uint32_t bsb = sbase + HG_B_BASE + buf * HG_BST;

#pragma unroll
        for (int kk = 0; kk < 2; kk++) {
            uint32_t af[4][4], bf[4][4];
            const int kb = kk * 16;
#pragma unroll
            for (int mt = 0; mt < 4; mt++) {
                uint32_t ad = asb + (uint32_t)((mbase + mt * 16 + a_row) * 40
                                               + kb + a_colh) * 2;
                LDSM_X4(af[mt], ad);
            }
#pragma unroll
            for (int ntp = 0; ntp < 4; ntp++) {
                uint32_t bd = bsb + (uint32_t)((kb + a_row) * 136
                                               + nbase + ntp * 16 + a_colh) * 2;
                LDSM_X4T(bf[ntp], bd);
            }
#pragma unroll
            for (int mt = 0; mt < 4; mt++)
#pragma unroll
                for (int ntp = 0; ntp < 4; ntp++) {
                    mma_f16(acc[mt][2 * ntp], af[mt], &bf[ntp][0]);
                    mma_f16(acc[mt][2 * ntp + 1], af[mt], &bf[ntp][2]);
                }
        }
        __syncthreads();
    }

#pragma unroll
    for (int mt = 0; mt < 4; mt++) {
        const int row = m0 + wm * 64 + mt * 16 + lr;
#pragma unroll
        for (int nt = 0; nt < 8; nt++) {
            const int col = n0 + wn * 64 + nt * 8 + kc * 2;
            if (half_out) {
                __half* Ch = (__half*)Cout;
                *(__half2*)&Ch[(size_t)row * N + col] =
                    __floats2half2_rn(acc[mt][nt][0], acc[mt][nt][1]);
                *(__half2*)&Ch[(size_t)(row + 8) * N + col] =
                    __floats2half2_rn(acc[mt][nt][2], acc[mt][nt][3]);
            } else {
                float* Cf = (float*)Cout;
                float b0 = bias[col], b1 = bias[col + 1];
                *(float2*)&Cf[(size_t)row * N + col] =
                    make_float2(acc[mt][nt][0] + b0, acc[mt][nt][1] + b1);
                *(float2*)&Cf[(size_t)(row + 8) * N + col] =
                    make_float2(acc[mt][nt][2] + b0, acc[mt][nt][3] + b1);
            }
        }
    }
}

// ---------------------------------------------------------------------------
// Causal flash attention, fp16 mma + ldmatrix. B-fragments now fetched TWO
// n-tiles per ldmatrix.x4 (40 ldsm / 64 mma per key-tile, was 72):
//   S (K natural, non-trans):  lanes (g=lane>>3): row np*16+(lane>>4)*8+(lane&7),
//       col kk*16+((lane>>3)&1)*8 -> {r0,r1}=nt 2np, {r2,r3}=nt 2np+1.
//   PV (V natural, trans):     hgemm X4T pattern: row kk*16+(lane&15),
//       col np*16+(lane>>4)*8.
// qt descending so long-causal-span blocks launch first.
// ---------------------------------------------------------------------------
#define AQ_PITCH 72
#define AT_QS_B 0
#define AT_PS_B 18432
#define AT_K_B  36864       // +9216 per buffer
#define AT_V_B  55296       // +9216 per buffer
#define ATH_SMEM_BYTES 73728

__global__ __launch_bounds__(256) void attn_h(const __half* __restrict__ qkv,
                                              __half* __restrict__ out) {
    extern __shared__ char smc[];
    const uint32_t sbase = smem_to_u32(smc);

    const int tid = threadIdx.x;
    const int wid = tid >> 5, lane = tid & 31;
    const int lr = lane >> 2, kc = lane & 3;
    const int qt = gridDim.x - 1 - blockIdx.x;   // long blocks first
    const int b = blockIdx.y >> 4;
    const int h = blockIdx.y & 15;
    const int row0 = wid * 16 + lr;
    const int row1 = row0 + 8;

    const __half* base = qkv + (size_t)b * T_SEQ * (3 * NEMB) + h * HD;

    auto load_kv = [&](int kt, int buf) {
        const uint32_t kb = sbase + AT_K_B + buf * 9216;
        const uint32_t vb = sbase + AT_V_B + buf * 9216;
        const __half* kp0 = base + NEMB + (size_t)(kt * 64) * (3 * NEMB);
#pragma unroll
        for (int i = 0; i < 2; i++) {
            int id = tid + i * 256;
            int r = id >> 3, cch = id & 7;
            const __half* g = kp0 + (size_t)r * (3 * NEMB) + cch * 8;
            CP_ASYNC16(kb + (uint32_t)(r * AQ_PITCH + cch * 8) * 2, g);
            CP_ASYNC16(vb + (uint32_t)(r * AQ_PITCH + cch * 8) * 2, g + NEMB);
        }
        CP_COMMIT();
    };

    load_kv(0, 0);
    {
        const uint32_t qb = sbase + AT_QS_B;
        const __half* qp0 = base + (size_t)(qt * 128) * (3 * NEMB);
#pragma unroll
        for (int i = 0; i < 4; i++) {
            int id = tid + i * 256;
            int r = id >> 3, cch = id & 7;
            CP_ASYNC16(qb + (uint32_t)(r * AQ_PITCH + cch * 8) * 2,
                       qp0 + (size_t)r * (3 * NEMB) + cch * 8);
        }
        CP_COMMIT();
    }

    float m0 = -1e30f, m1 = -1e30f, l0 = 0.f, l1 = 0.f;
    float O[8][4];
#pragma unroll
    for (int nt = 0; nt < 8; nt++)
#pragma unroll
        for (int r = 0; r < 4; r++) O[nt][r] = 0.f;

    const int a_row = (lane & 15);
    const int a_colh = (lane >> 4) * 8;
    // S B-fragment lane mapping (two n-tiles per x4)
    const int s_nrow = (lane >> 4) * 8 + (lane & 7);
    const int s_koff = ((lane >> 3) & 1) * 8;

    const int NT = 2 * qt + 2;
    for (int kt = 0; kt < NT; kt++) {
        const int buf = kt & 1;
        CP_WAIT0();
        __syncthreads();
        if (kt + 1 < NT) load_kv(kt + 1, buf ^ 1);

        const uint32_t kbuf = sbase + AT_K_B + buf * 9216;
        const uint32_t vbuf = sbase + AT_V_B + buf * 9216;
        const uint32_t qb = sbase + AT_QS_B;
        const uint32_t pb = sbase + AT_PS_B;

        // ---- S = Q K^T : per k16 step, 1 A-x4 + 4 B-x4 -> 8 MMAs
        float s[8][4];
#pragma unroll
        for (int nt = 0; nt < 8; nt++)
#pragma unroll
            for (int r = 0; r < 4; r++) s[nt][r] = 0.f;

#pragma unroll
        for (int kk = 0; kk < 4; kk++) {
            uint32_t af[4], bf[4][4];
            LDSM_X4(af, qb + (uint32_t)((wid * 16 + a_row) * AQ_PITCH
                                        + kk * 16 + a_colh) * 2);
#pragma unroll
            for (int np = 0; np < 4; np++) {
                LDSM_X4(bf[np], kbuf + (uint32_t)((np * 16 + s_nrow) * AQ_PITCH
                                                  + kk * 16 + s_koff) * 2);
            }
#pragma unroll
            for (int np = 0; np < 4; np++) {
                mma_f16(s[2 * np], af, &bf[np][0]);
                mma_f16(s[2 * np + 1], af, &bf[np][2]);
            }
        }

#pragma unroll
        for (int nt = 0; nt < 8; nt++)
#pragma unroll
            for (int r = 0; r < 4; r++) s[nt][r] *= 0.125f;

        if (kt >= 2 * qt) {
            const int grow0 = qt * 128 + row0;
            const int grow1 = grow0 + 8;
#pragma unroll
            for (int nt = 0; nt < 8; nt++) {
                int gc = kt * 64 + nt * 8 + kc * 2;
                if (gc > grow0)     s[nt][0] = -1e30f;
                if (gc + 1 > grow0) s[nt][1] = -1e30f;
                if (gc > grow1)     s[nt][2] = -1e30f;
                if (gc + 1 > grow1) s[nt][3] = -1e30f;
            }
        }

        // ---- online softmax
        float pm0 = -1e30f, pm1 = -1e30f;
#pragma unroll
        for (int nt = 0; nt < 8; nt++) {
            pm0 = fmaxf(pm0, fmaxf(s[nt][0], s[nt][1]));
            pm1 = fmaxf(pm1, fmaxf(s[nt][2], s[nt][3]));
        }
        pm0 = fmaxf(pm0, __shfl_xor_sync(0xffffffffu, pm0, 1));
        pm0 = fmaxf(pm0, __shfl_xor_sync(0xffffffffu, pm0, 2));
        pm1 = fmaxf(pm1, __shfl_xor_sync(0xffffffffu, pm1, 1));
        pm1 = fmaxf(pm1, __shfl_xor_sync(0xffffffffu, pm1, 2));

        float mn0 = fmaxf(m0, pm0), mn1 = fmaxf(m1, pm1);
        float al0 = __expf(m0 - mn0), al1 = __expf(m1 - mn1);
        m0 = mn0; m1 = mn1;

        float rs0 = 0.f, rs1 = 0.f;
#pragma unroll
        for (int nt = 0; nt < 8; nt++) {
            s[nt][0] = __expf(s[nt][0] - mn0); rs0 += s[nt][0];
            s[nt][1] = __expf(s[nt][1] - mn0); rs0 += s[nt][1];
            s[nt][2] = __expf(s[nt][2] - mn1); rs1 += s[nt][2];
            s[nt][3] = __expf(s[nt][3] - mn1); rs1 += s[nt][3];
        }
        rs0 += __shfl_xor_sync(0xffffffffu, rs0, 1);
        rs0 += __shfl_xor_sync(0xffffffffu, rs0, 2);
        rs1 += __shfl_xor_sync(0xffffffffu, rs1, 1);
        rs1 += __shfl_xor_sync(0xffffffffu, rs1, 2);
        l0 = l0 * al0 + rs0;
        l1 = l1 * al1 + rs1;

#pragma unroll
        for (int nt = 0; nt < 8; nt++) {
            O[nt][0] *= al0; O[nt][1] *= al0;
            O[nt][2] *= al1; O[nt][3] *= al1;
        }

        // ---- P (half) -> smem (warp-private), then O += P V
        {
            __half* Ph = (__half*)(smc + AT_PS_B);
#pragma unroll
            for (int nt = 0; nt < 8; nt++) {
                *(__half2*)&Ph[row0 * AQ_PITCH + nt * 8 + kc * 2] =
                    __floats2half2_rn(s[nt][0], s[nt][1]);
                *(__half2*)&Ph[row1 * AQ_PITCH + nt * 8 + kc * 2] =
                    __floats2half2_rn(s[nt][2], s[nt][3]);
            }
        }
        __syncwarp();

#pragma unroll
        for (int kk = 0; kk < 4; kk++) {
            uint32_t af[4], bf[4][4];
            LDSM_X4(af, pb + (uint32_t)((wid * 16 + a_row) * AQ_PITCH
                                        + kk * 16 + a_colh) * 2);
#pragma unroll
            for (int np = 0; np < 4; np++) {
                LDSM_X4T(bf[np], vbuf + (uint32_t)((kk * 16 + a_row) * AQ_PITCH
                                                   + np * 16 + a_colh) * 2);
            }
#pragma unroll
            for (int np = 0; np < 4; np++) {
                mma_f16(O[2 * np], af, &bf[np][0]);
                mma_f16(O[2 * np + 1], af, &bf[np][2]);
            }
        }
    }

    // Epilogue
    const float inv0 = 1.0f / l0, inv1 = 1.0f / l1;
    const size_t rg0 = (size_t)b * T_SEQ + qt * 128 + row0;
#pragma unroll
    for (int nt = 0; nt < 8; nt++) {
        int col = h * HD + nt * 8 + kc * 2;
        *(__half2*)&out[rg0 * NEMB + col] =
            __floats2half2_rn(O[nt][0] * inv0, O[nt][1] * inv0);
        *(__half2*)&out[(rg0 + 8) * NEMB + col] =
            __floats2half2_rn(O[nt][2] * inv1, O[nt][3] * inv1);
    }
}

// ---------------------------------------------------------------------------
// kernel_launch
// ---------------------------------------------------------------------------
extern "C" void kernel_launch(void* const* d_in, const int* in_sizes, int n_in,
                              void* d_out, int out_size) {
    const float* x     = (const float*)d_in[0];
    const float* w_qkv = (const float*)d_in[1];
    const float* w_out = (const float*)d_in[2];
    const float* b_out = (const float*)d_in[3];
    float* out = (float*)d_out;

    __half *xh, *wqkvh, *wouth, *qkvh, *attnh;
    cudaGetSymbolAddress((void**)&xh, g_xh);
    cudaGetSymbolAddress((void**)&wqkvh, g_wqkvh);
    cudaGetSymbolAddress((void**)&wouth, g_wouth);
    cudaGetSymbolAddress((void**)&qkvh, g_qkvh);
    cudaGetSymbolAddress((void**)&attnh, g_attnh);

    cudaFuncSetAttribute(hgemm, cudaFuncAttributeMaxDynamicSharedMemorySize, HG_SMEM_BYTES);
    cudaFuncSetAttribute(attn_h, cudaFuncAttributeMaxDynamicSharedMemorySize, ATH_SMEM_BYTES);

    const int M = BATCH * T_SEQ;    // 8192

    f2h<<<512, 256>>>(x, xh, M * NEMB);
    f2h<<<512, 256>>>(w_qkv, wqkvh, NEMB * 3 * NEMB);
    f2h<<<256, 256>>>(w_out, wouth, NEMB * NEMB);

    hgemm<<<dim3(3 * NEMB / 128, M / 128), 128, HG_SMEM_BYTES>>>(
        xh, wqkvh, nullptr, qkvh, M, 3 * NEMB, NEMB, 1);

    attn_h<<<dim3(T_SEQ / 128, BATCH * NHEADS), 256, ATH_SMEM_BYTES>>>(qkvh, attnh);

    hgemm<<<dim3(NEMB / 128, M / 128), 128, HG_SMEM_BYTES>>>(
        attnh, wouth, b_out, out, M, NEMB, NEMB, 0);
}

// round 13
// speedup vs baseline: 1.0549x; 1.0549x over previous
#include <cuda_runtime.h>
#include <cuda_fp16.h>
#include <cstdint>

#define T_SEQ 2048
#define NHEADS 16
#define NEMB 1024
#define HD 64
#define BATCH 4

// ---------------------------------------------------------------------------
// Scratch (no allocation allowed anywhere) — half-precision pipeline
// ---------------------------------------------------------------------------
__device__ __half g_xh[(size_t)BATCH * T_SEQ * NEMB];
__device__ __half g_wqkvh[(size_t)NEMB * 3 * NEMB];
__device__ __half g_wouth[(size_t)NEMB * NEMB];
__device__ __half g_qkvh[(size_t)BATCH * T_SEQ * 3 * NEMB];
__device__ __half g_attnh[(size_t)BATCH * T_SEQ * NEMB];

// ---------------------------------------------------------------------------
// PTX helpers (baseline PTX only — sm_103 non-'a' target)
// ---------------------------------------------------------------------------
__device__ __forceinline__ uint32_t smem_to_u32(const void* p) {
    uint32_t a;
    asm("{ .reg .u64 t; cvta.to.shared.u64 t, %1; cvt.u32.u64 %0, t; }" : "=r"(a) : "l"(p));
    return a;
}
__device__ __forceinline__ float exp2_fast(float x) {
    float y;
    asm("ex2.approx.ftz.f32 %0, %1;" : "=f"(y) : "f"(x));
    return y;
}
__device__ __forceinline__ void mma_f16(float* d, const uint32_t* a, const uint32_t* b) {
    asm volatile(
        "mma.sync.aligned.m16n8k16.row.col.f32.f16.f16.f32 "
        "{%0,%1,%2,%3}, {%4,%5,%6,%7}, {%8,%9}, {%0,%1,%2,%3};"
        : "+f"(d[0]), "+f"(d[1]), "+f"(d[2]), "+f"(d[3])
        : "r"(a[0]), "r"(a[1]), "r"(a[2]), "r"(a[3]), "r"(b[0]), "r"(b[1]));
}
#define LDSM_X4(r, addr) \
    asm volatile("ldmatrix.sync.aligned.m8n8.x4.shared.b16 {%0,%1,%2,%3}, [%4];" \
                 : "=r"((r)[0]), "=r"((r)[1]), "=r"((r)[2]), "=r"((r)[3]) : "r"(addr))
#define LDSM_X4T(r, addr) \
    asm volatile("ldmatrix.sync.aligned.m8n8.x4.trans.shared.b16 {%0,%1,%2,%3}, [%4];" \
                 : "=r"((r)[0]), "=r"((r)[1]), "=r"((r)[2]), "=r"((r)[3]) : "r"(addr))
#define CP_ASYNC16(dst, src) \
    asm volatile("cp.async.cg.shared.global [%0], [%1], 16;" :: "r"(dst), "l"(src))
#define CP_COMMIT()  asm volatile("cp.async.commit_group;" ::: "memory")
#define CP_WAIT1()   asm volatile("cp.async.wait_group 1;" ::: "memory")
#define CP_WAIT0()   asm volatile("cp.async.wait_group 0;" ::: "memory")

// ---------------------------------------------------------------------------
// fp32 -> fp16 elementwise convert (n % 4 == 0)
// ---------------------------------------------------------------------------
__global__ void f2h(const float* __restrict__ in, __half* __restrict__ out, int n) {
    int stride = gridDim.x * blockDim.x;
    for (int i = blockIdx.x * blockDim.x + threadIdx.x; i * 4 < n; i += stride) {
        float4 v = ((const float4*)in)[i];
        __half2* o = (__half2*)(out + (size_t)i * 4);
        o[0] = __floats2half2_rn(v.x, v.y);
        o[1] = __floats2half2_rn(v.z, v.w);
    }
}

// w_qkv convert with Q-column scaling: cols [0,1024) of the 3072-wide matrix
// are the Q projection; fold 1/sqrt(D) * log2(e) = 0.125*1.44269504 into them
// so attention scores arrive pre-scaled in the log2 domain.
__global__ void f2h_wqkv(const float* __restrict__ in, __half* __restrict__ out, int n) {
    const float QS = 0.18033688f;   // 0.125 * log2(e)
    int stride = gridDim.x * blockDim.x;
    for (int i = blockIdx.x * blockDim.x + threadIdx.x; i * 4 < n; i += stride) {
        float4 v = ((const float4*)in)[i];
        int col = (i * 4) % (3 * NEMB);       // 1024-boundary is float4-aligned
        float s = (col < NEMB) ? QS : 1.0f;
        __half2* o = (__half2*)(out + (size_t)i * 4);
        o[0] = __floats2half2_rn(v.x * s, v.y * s);
        o[1] = __floats2half2_rn(v.z * s, v.w * s);
    }
}

// ---------------------------------------------------------------------------
// fp16 mma.sync GEMM v3 (unchanged from R11, measured 165.9us):
// CTA 128x128, 128 threads / 4 warps, warp tile 64x64, 2-stage cp.async.
// ---------------------------------------------------------------------------
#define HG_AST 10240                 // A stage bytes (128*40*2)
#define HG_BST 8704                  // B stage bytes (32*136*2)
#define HG_B_BASE (2 * HG_AST)
#define HG_SMEM_BYTES (2 * (HG_AST + HG_BST))   // 37888

__global__ __launch_bounds__(128) void hgemm(const __half* __restrict__ A,
                                             const __half* __restrict__ B,
                                             const float* __restrict__ bias,
                                             void* __restrict__ Cout,
                                             int M, int N, int K, int half_out) {
    extern __shared__ char smc[];
    const uint32_t sbase = smem_to_u32(smc);
    const int tid = threadIdx.x;
    const int wid = tid >> 5, lane = tid & 31;
    const int wm = wid & 1, wn = wid >> 1;
    const int lr = lane >> 2, kc = lane & 3;
    const int m0 = blockIdx.y * 128, n0 = blockIdx.x * 128;

    auto load_tile = [&](int c, int st) {
        const uint32_t asb = sbase + st * HG_AST;
        const uint32_t bsb = sbase + HG_B_BASE + st * HG_BST;
        const __half* Ac = A + (size_t)m0 * K + c * 32;
        const __half* Bc = B + (size_t)(c * 32) * N + n0;
#pragma unroll
        for (int i = 0; i < 4; i++) {
            int id = tid + i * 128;
            int am = id >> 2, ak = id & 3;
            CP_ASYNC16(asb + (uint32_t)(am * 40 + ak * 8) * 2,
                       Ac + (size_t)am * K + ak * 8);
            int bk = id >> 4, bn = id & 15;
            CP_ASYNC16(bsb + (uint32_t)(bk * 136 + bn * 8) * 2,
                       Bc + (size_t)bk * N + bn * 8);
        }
        CP_COMMIT();
    };

    float acc[4][8][4];
#pragma unroll
    for (int i = 0; i < 4; i++)
#pragma unroll
        for (int j = 0; j < 8; j++)
#pragma unroll
            for (int r = 0; r < 4; r++) acc[i][j][r] = 0.f;

    const int NT = K >> 5;
    load_tile(0, 0);

    const int mbase = wm * 64, nbase = wn * 64;
    const int a_row = (lane & 15);
    const int a_colh = (lane >> 4) * 8;

    for (int c = 0; c < NT; c++) {
        const int buf = c & 1;
        if (c + 1 < NT) { load_tile(c + 1, buf ^ 1); CP_WAIT1(); }
        else            { CP_WAIT0(); }
        __syncthreads();

        const uint32_t asb = sbase + buf * HG_AST;
        const uint32_t bsb = sbase + HG_B_BASE + buf * HG_BST;

#pragma unroll
        for (int kk = 0; kk < 2; kk++) {
            uint32_t af[4][4], bf[4][4];
            const int kb = kk * 16;
#pragma unroll
            for (int mt = 0; mt < 4; mt++) {
                uint32_t ad = asb + (uint32_t)((mbase + mt * 16 + a_row) * 40
                                               + kb + a_colh) * 2;
                LDSM_X4(af[mt], ad);
            }
#pragma unroll
            for (int ntp = 0; ntp < 4; ntp++) {
                uint32_t bd = bsb + (uint32_t)((kb + a_row) * 136
                                               + nbase + ntp * 16 + a_colh) * 2;
                LDSM_X4T(bf[ntp], bd);
            }
#pragma unroll
            for (int mt = 0; mt < 4; mt++)
#pragma unroll
                for (int ntp = 0; ntp < 4; ntp++) {
                    mma_f16(acc[mt][2 * ntp], af[mt], &bf[ntp][0]);
                    mma_f16(acc[mt][2 * ntp + 1], af[mt], &bf[ntp][2]);
                }
        }
        __syncthreads();
    }

#pragma unroll
    for (int mt = 0; mt < 4; mt++) {
        const int row = m0 + wm * 64 + mt * 16 + lr;
#pragma unroll
        for (int nt = 0; nt < 8; nt++) {
            const int col = n0 + wn * 64 + nt * 8 + kc * 2;
            if (half_out) {
                __half* Ch = (__half*)Cout;
                *(__half2*)&Ch[(size_t)row * N + col] =
                    __floats2half2_rn(acc[mt][nt][0], acc[mt][nt][1]);
                *(__half2*)&Ch[(size_t)(row + 8) * N + col] =
                    __floats2half2_rn(acc[mt][nt][2], acc[mt][nt][3]);
            } else {
                float* Cf = (float*)Cout;
                float b0 = bias[col], b1 = bias[col + 1];
                *(float2*)&Cf[(size_t)row * N + col] =
                    make_float2(acc[mt][nt][0] + b0, acc[mt][nt][1] + b1);
                *(float2*)&Cf[(size_t)(row + 8) * N + col] =
                    make_float2(acc[mt][nt][2] + b0, acc[mt][nt][3] + b1);
            }
        }
    }
}

// ---------------------------------------------------------------------------
// Causal flash attention, fp16 mma + ldmatrix.
// Softmax in log2 domain (scale folded into Q weights): P = exp2(s - m),
// no per-score multiplies. Tail reordered: P store + O rescale + PV MMAs
// issue BEFORE the sum shfl-chain / l update (shfl latency hides under HMMA).
// ---------------------------------------------------------------------------
#define AQ_PITCH 72
#define AT_QS_B 0
#define AT_PS_B 18432
#define AT_K_B  36864       // +9216 per buffer
#define AT_V_B  55296       // +9216 per buffer
#define ATH_SMEM_BYTES 73728

__global__ __launch_bounds__(256) void attn_h(const __half* __restrict__ qkv,
                                              __half* __restrict__ out) {
    extern __shared__ char smc[];
    const uint32_t sbase = smem_to_u32(smc);

    const int tid = threadIdx.x;
    const int wid = tid >> 5, lane = tid & 31;
    const int lr = lane >> 2, kc = lane & 3;
    const int qt = gridDim.x - 1 - blockIdx.x;   // long blocks first
    const int b = blockIdx.y >> 4;
    const int h = blockIdx.y & 15;
    const int row0 = wid * 16 + lr;
    const int row1 = row0 + 8;

    const __half* base = qkv + (size_t)b * T_SEQ * (3 * NEMB) + h * HD;

    auto load_kv = [&](int kt, int buf) {
        const uint32_t kb = sbase + AT_K_B + buf * 9216;
        const uint32_t vb = sbase + AT_V_B + buf * 9216;
        const __half* kp0 = base + NEMB + (size_t)(kt * 64) * (3 * NEMB);
#pragma unroll
        for (int i = 0; i < 2; i++) {
            int id = tid + i * 256;
            int r = id >> 3, cch = id & 7;
            const __half* g = kp0 + (size_t)r * (3 * NEMB) + cch * 8;
            CP_ASYNC16(kb + (uint32_t)(r * AQ_PITCH + cch * 8) * 2, g);
            CP_ASYNC16(vb + (uint32_t)(r * AQ_PITCH + cch * 8) * 2, g + NEMB);
        }
        CP_COMMIT();
    };

    load_kv(0, 0);
    {
        const uint32_t qb = sbase + AT_QS_B;
        const __half* qp0 = base + (size_t)(qt * 128) * (3 * NEMB);
#pragma unroll
        for (int i = 0; i < 4; i++) {
            int id = tid + i * 256;
            int r = id >> 3, cch = id & 7;
            CP_ASYNC16(qb + (uint32_t)(r * AQ_PITCH + cch * 8) * 2,
                       qp0 + (size_t)r * (3 * NEMB) + cch * 8);
        }
        CP_COMMIT();
    }

    float m0 = -1e30f, m1 = -1e30f, l0 = 0.f, l1 = 0.f;
    float O[8][4];
#pragma unroll
    for (int nt = 0; nt < 8; nt++)
#pragma unroll
        for (int r = 0; r < 4; r++) O[nt][r] = 0.f;

    const int a_row = (lane & 15);
    const int a_colh = (lane >> 4) * 8;
    const int s_nrow = (lane >> 4) * 8 + (lane & 7);
    const int s_koff = ((lane >> 3) & 1) * 8;

    const int NT = 2 * qt + 2;
    for (int kt = 0; kt < NT; kt++) {
        const int buf = kt & 1;
        CP_WAIT0();
        __syncthreads();
        if (kt + 1 < NT) load_kv(kt + 1, buf ^ 1);

        const uint32_t kbuf = sbase + AT_K_B + buf * 9216;
        const uint32_t vbuf = sbase + AT_V_B + buf * 9216;
        const uint32_t qb = sbase + AT_QS_B;
        const uint32_t pb = sbase + AT_PS_B;

        // ---- S = Q K^T (already in log2 domain via Q-weight scaling)
        float s[8][4];
#pragma unroll
        for (int nt = 0; nt < 8; nt++)
#pragma unroll
            for (int r = 0; r < 4; r++) s[nt][r] = 0.f;

#pragma unroll
        for (int kk = 0; kk < 4; kk++) {
            uint32_t af[4], bf[4][4];
            LDSM_X4(af, qb + (uint32_t)((wid * 16 + a_row) * AQ_PITCH
                                        + kk * 16 + a_colh) * 2);
#pragma unroll
            for (int np = 0; np < 4; np++) {
                LDSM_X4(bf[np], kbuf + (uint32_t)((np * 16 + s_nrow) * AQ_PITCH
                                                  + kk * 16 + s_koff) * 2);
            }
#pragma unroll
            for (int np = 0; np < 4; np++) {
                mma_f16(s[2 * np], af, &bf[np][0]);
                mma_f16(s[2 * np + 1], af, &bf[np][2]);
            }
        }

        if (kt >= 2 * qt) {                  // causal mask (diagonal region)
            const int grow0 = qt * 128 + row0;
            const int grow1 = grow0 + 8;
#pragma unroll
            for (int nt = 0; nt < 8; nt++) {
                int gc = kt * 64 + nt * 8 + kc * 2;
                if (gc > grow0)     s[nt][0] = -1e30f;
                if (gc + 1 > grow0) s[nt][1] = -1e30f;
                if (gc > grow1)     s[nt][2] = -1e30f;
                if (gc + 1 > grow1) s[nt][3] = -1e30f;
            }
        }

        // ---- row max (quad reduce)
        float pm0 = -1e30f, pm1 = -1e30f;
#pragma unroll
        for (int nt = 0; nt < 8; nt++) {
            pm0 = fmaxf(pm0, fmaxf(s[nt][0], s[nt][1]));
            pm1 = fmaxf(pm1, fmaxf(s[nt][2], s[nt][3]));
        }
        pm0 = fmaxf(pm0, __shfl_xor_sync(0xffffffffu, pm0, 1));
        pm0 = fmaxf(pm0, __shfl_xor_sync(0xffffffffu, pm0, 2));
        pm1 = fmaxf(pm1, __shfl_xor_sync(0xffffffffu, pm1, 1));
        pm1 = fmaxf(pm1, __shfl_xor_sync(0xffffffffu, pm1, 2));

        float mn0 = fmaxf(m0, pm0), mn1 = fmaxf(m1, pm1);
        float al0 = exp2_fast(m0 - mn0), al1 = exp2_fast(m1 - mn1);
        m0 = mn0; m1 = mn1;

        // ---- exps (pure EX2) with partial sums in-loop
        float rsa0 = 0.f, rsb0 = 0.f, rsa1 = 0.f, rsb1 = 0.f;
#pragma unroll
        for (int nt = 0; nt < 8; nt++) {
            s[nt][0] = exp2_fast(s[nt][0] - mn0); rsa0 += s[nt][0];
            s[nt][1] = exp2_fast(s[nt][1] - mn0); rsb0 += s[nt][1];
            s[nt][2] = exp2_fast(s[nt][2] - mn1); rsa1 += s[nt][2];
            s[nt][3] = exp2_fast(s[nt][3] - mn1); rsb1 += s[nt][3];
        }

        // ---- P store (needs only exps) + O rescale + PV MMAs FIRST
        {
            __half* Ph = (__half*)(smc + AT_PS_B);
#pragma unroll
            for (int nt = 0; nt < 8; nt++) {
                *(__half2*)&Ph[row0 * AQ_PITCH + nt * 8 + kc * 2] =
                    __floats2half2_rn(s[nt][0], s[nt][1]);
                *(__half2*)&Ph[row1 * AQ_PITCH + nt * 8 + kc * 2] =
                    __floats2half2_rn(s[nt][2], s[nt][3]);
            }
        }
        __syncwarp();

#pragma unroll
        for (int nt = 0; nt < 8; nt++) {
            O[nt][0] *= al0; O[nt][1] *= al0;
            O[nt][2] *= al1; O[nt][3] *= al1;
        }

#pragma unroll
        for (int kk = 0; kk < 4; kk++) {
            uint32_t af[4], bf[4][4];
            LDSM_X4(af, pb + (uint32_t)((wid * 16 + a_row) * AQ_PITCH
                                        + kk * 16 + a_colh) * 2);
#pragma unroll
            for (int np = 0; np < 4; np++) {
                LDSM_X4T(bf[np], vbuf + (uint32_t)((kk * 16 + a_row) * AQ_PITCH
                                                   + np * 16 + a_colh) * 2);
            }
#pragma unroll
            for (int np = 0; np < 4; np++) {
                mma_f16(O[2 * np], af, &bf[np][0]);
                mma_f16(O[2 * np + 1], af, &bf[np][2]);
            }
        }

        // ---- sum reduce + l update LAST (shfl latency hides under HMMAs)
        float rs0 = rsa0 + rsb0, rs1 = rsa1 + rsb1;
        rs0 += __shfl_xor_sync(0xffffffffu, rs0, 1);
        rs0 += __shfl_xor_sync(0xffffffffu, rs0, 2);
        rs1 += __shfl_xor_sync(0xffffffffu, rs1, 1);
        rs1 += __shfl_xor_sync(0xffffffffu, rs1, 2);
        l0 = l0 * al0 + rs0;
        l1 = l1 * al1 + rs1;
    }

    // Epilogue
    const float inv0 = 1.0f / l0, inv1 = 1.0f / l1;
    const size_t rg0 = (size_t)b * T_SEQ + qt * 128 + row0;
#pragma unroll
    for (int nt = 0; nt < 8; nt++) {
        int col = h * HD + nt * 8 + kc * 2;
        *(__half2*)&out[rg0 * NEMB + col] =
            __floats2half2_rn(O[nt][0] * inv0, O[nt][1] * inv0);
        *(__half2*)&out[(rg0 + 8) * NEMB + col] =
            __floats2half2_rn(O[nt][2] * inv1, O[nt][3] * inv1);
    }
}

// ---------------------------------------------------------------------------
// kernel_launch
// ---------------------------------------------------------------------------
extern "C" void kernel_launch(void* const* d_in, const int* in_sizes, int n_in,
                              void* d_out, int out_size) {
    const float* x     = (const float*)d_in[0];
    const float* w_qkv = (const float*)d_in[1];
    const float* w_out = (const float*)d_in[2];
    const float* b_out = (const float*)d_in[3];
    float* out = (float*)d_out;

    __half *xh, *wqkvh, *wouth, *qkvh, *attnh;
    cudaGetSymbolAddress((void**)&xh, g_xh);
    cudaGetSymbolAddress((void**)&wqkvh, g_wqkvh);
    cudaGetSymbolAddress((void**)&wouth, g_wouth);
    cudaGetSymbolAddress((void**)&qkvh, g_qkvh);
    cudaGetSymbolAddress((void**)&attnh, g_attnh);

    cudaFuncSetAttribute(hgemm, cudaFuncAttributeMaxDynamicSharedMemorySize, HG_SMEM_BYTES);
    cudaFuncSetAttribute(attn_h, cudaFuncAttributeMaxDynamicSharedMemorySize, ATH_SMEM_BYTES);

    const int M = BATCH * T_SEQ;    // 8192

    f2h<<<512, 256>>>(x, xh, M * NEMB);
    f2h_wqkv<<<512, 256>>>(w_qkv, wqkvh, NEMB * 3 * NEMB);
    f2h<<<256, 256>>>(w_out, wouth, NEMB * NEMB);

    hgemm<<<dim3(3 * NEMB / 128, M / 128), 128, HG_SMEM_BYTES>>>(
        xh, wqkvh, nullptr, qkvh, M, 3 * NEMB, NEMB, 1);

    attn_h<<<dim3(T_SEQ / 128, BATCH * NHEADS), 256, ATH_SMEM_BYTES>>>(qkvh, attnh);

    hgemm<<<dim3(NEMB / 128, M / 128), 128, HG_SMEM_BYTES>>>(
        attnh, wouth, b_out, out, M, NEMB, NEMB, 0);
}

// round 14
// speedup vs baseline: 1.0945x; 1.0375x over previous
#include <cuda_runtime.h>
#include <cuda_fp16.h>
#include <cstdint>

#define T_SEQ 2048
#define NHEADS 16
#define NEMB 1024
#define HD 64
#define BATCH 4

// ---------------------------------------------------------------------------
// Scratch (no allocation allowed anywhere) — half-precision pipeline
// ---------------------------------------------------------------------------
__device__ __half g_xh[(size_t)BATCH * T_SEQ * NEMB];
__device__ __half g_wqkvh[(size_t)NEMB * 3 * NEMB];
__device__ __half g_wouth[(size_t)NEMB * NEMB];
__device__ __half g_qkvh[(size_t)BATCH * T_SEQ * 3 * NEMB];
__device__ __half g_attnh[(size_t)BATCH * T_SEQ * NEMB];

// ---------------------------------------------------------------------------
// PTX helpers (baseline PTX only — sm_103 non-'a' target)
// ---------------------------------------------------------------------------
__device__ __forceinline__ uint32_t smem_to_u32(const void* p) {
    uint32_t a;
    asm("{ .reg .u64 t; cvta.to.shared.u64 t, %1; cvt.u32.u64 %0, t; }" : "=r"(a) : "l"(p));
    return a;
}
__device__ __forceinline__ float exp2_fast(float x) {
    float y;
    asm("ex2.approx.ftz.f32 %0, %1;" : "=f"(y) : "f"(x));
    return y;
}
__device__ __forceinline__ uint32_t packh2(float a, float b) {
    __half2 h = __floats2half2_rn(a, b);
    return *(uint32_t*)&h;
}
__device__ __forceinline__ void mma_f16(float* d, const uint32_t* a, const uint32_t* b) {
    asm volatile(
        "mma.sync.aligned.m16n8k16.row.col.f32.f16.f16.f32 "
        "{%0,%1,%2,%3}, {%4,%5,%6,%7}, {%8,%9}, {%0,%1,%2,%3};"
        : "+f"(d[0]), "+f"(d[1]), "+f"(d[2]), "+f"(d[3])
        : "r"(a[0]), "r"(a[1]), "r"(a[2]), "r"(a[3]), "r"(b[0]), "r"(b[1]));
}
#define LDSM_X4(r, addr) \
    asm volatile("ldmatrix.sync.aligned.m8n8.x4.shared.b16 {%0,%1,%2,%3}, [%4];" \
                 : "=r"((r)[0]), "=r"((r)[1]), "=r"((r)[2]), "=r"((r)[3]) : "r"(addr))
#define LDSM_X4T(r, addr) \
    asm volatile("ldmatrix.sync.aligned.m8n8.x4.trans.shared.b16 {%0,%1,%2,%3}, [%4];" \
                 : "=r"((r)[0]), "=r"((r)[1]), "=r"((r)[2]), "=r"((r)[3]) : "r"(addr))
#define CP_ASYNC16(dst, src) \
    asm volatile("cp.async.cg.shared.global [%0], [%1], 16;" :: "r"(dst), "l"(src))
#define CP_COMMIT()  asm volatile("cp.async.commit_group;" ::: "memory")
#define CP_WAIT1()   asm volatile("cp.async.wait_group 1;" ::: "memory")
#define CP_WAIT0()   asm volatile("cp.async.wait_group 0;" ::: "memory")

// ---------------------------------------------------------------------------
// fp32 -> fp16 elementwise convert (n % 4 == 0)
// ---------------------------------------------------------------------------
__global__ void f2h(const float* __restrict__ in, __half* __restrict__ out, int n) {
    int stride = gridDim.x * blockDim.x;
    for (int i = blockIdx.x * blockDim.x + threadIdx.x; i * 4 < n; i += stride) {
        float4 v = ((const float4*)in)[i];
        __half2* o = (__half2*)(out + (size_t)i * 4);
        o[0] = __floats2half2_rn(v.x, v.y);
        o[1] = __floats2half2_rn(v.z, v.w);
    }
}

// w_qkv convert with Q-column scaling (log2-domain softmax)
__global__ void f2h_wqkv(const float* __restrict__ in, __half* __restrict__ out, int n) {
    const float QS = 0.18033688f;   // 0.125 * log2(e)
    int stride = gridDim.x * blockDim.x;
    for (int i = blockIdx.x * blockDim.x + threadIdx.x; i * 4 < n; i += stride) {
        float4 v = ((const float4*)in)[i];
        int col = (i * 4) % (3 * NEMB);
        float s = (col < NEMB) ? QS : 1.0f;
        __half2* o = (__half2*)(out + (size_t)i * 4);
        o[0] = __floats2half2_rn(v.x * s, v.y * s);
        o[1] = __floats2half2_rn(v.z * s, v.w * s);
    }
}

// ---------------------------------------------------------------------------
// fp16 mma.sync GEMM v3 (unchanged, measured 166us):
// CTA 128x128, 128 threads / 4 warps, warp tile 64x64, 2-stage cp.async.
// ---------------------------------------------------------------------------
#define HG_AST 10240
#define HG_BST 8704
#define HG_B_BASE (2 * HG_AST)
#define HG_SMEM_BYTES (2 * (HG_AST + HG_BST))   // 37888

__global__ __launch_bounds__(128) void hgemm(const __half* __restrict__ A,
                                             const __half* __restrict__ B,
                                             const float* __restrict__ bias,
                                             void* __restrict__ Cout,
                                             int M, int N, int K, int half_out) {
    extern __shared__ char smc[];
    const uint32_t sbase = smem_to_u32(smc);
    const int tid = threadIdx.x;
    const int wid = tid >> 5, lane = tid & 31;
    const int wm = wid & 1, wn = wid >> 1;
    const int lr = lane >> 2, kc = lane & 3;
    const int m0 = blockIdx.y * 128, n0 = blockIdx.x * 128;

    auto load_tile = [&](int c, int st) {
        const uint32_t asb = sbase + st * HG_AST;
        const uint32_t bsb = sbase + HG_B_BASE + st * HG_BST;
        const __half* Ac = A + (size_t)m0 * K + c * 32;
        const __half* Bc = B + (size_t)(c * 32) * N + n0;
#pragma unroll
        for (int i = 0; i < 4; i++) {
            int id = tid + i * 128;
            int am = id >> 2, ak = id & 3;
            CP_ASYNC16(asb + (uint32_t)(am * 40 + ak * 8) * 2,
                       Ac + (size_t)am * K + ak * 8);
            int bk = id >> 4, bn = id & 15;
            CP_ASYNC16(bsb + (uint32_t)(bk * 136 + bn * 8) * 2,
                       Bc + (size_t)bk * N + bn * 8);
        }
        CP_COMMIT();
    };

    float acc[4][8][4];
#pragma unroll
    for (int i = 0; i < 4; i++)
#pragma unroll
        for (int j = 0; j < 8; j++)
#pragma unroll
            for (int r = 0; r < 4; r++) acc[i][j][r] = 0.f;

    const int NT = K >> 5;
    load_tile(0, 0);

    const int mbase = wm * 64, nbase = wn * 64;
    const int a_row = (lane & 15);
    const int a_colh = (lane >> 4) * 8;

    for (int c = 0; c < NT; c++) {
        const int buf = c & 1;
        if (c + 1 < NT) { load_tile(c + 1, buf ^ 1); CP_WAIT1(); }
        else            { CP_WAIT0(); }
        __syncthreads();

        const uint32_t asb = sbase + buf * HG_AST;
        const uint32_t bsb = sbase + HG_B_BASE + buf * HG_BST;

#pragma unroll
        for (int kk = 0; kk < 2; kk++) {
            uint32_t af[4][4], bf[4][4];
            const int kb = kk * 16;
#pragma unroll
            for (int mt = 0; mt < 4; mt++) {
                uint32_t ad = asb + (uint32_t)((mbase + mt * 16 + a_row) * 40
                                               + kb + a_colh) * 2;
                LDSM_X4(af[mt], ad);
            }
#pragma unroll
            for (int ntp = 0; ntp < 4; ntp++) {
                uint32_t bd = bsb + (uint32_t)((kb + a_row) * 136
                                               + nbase + ntp * 16 + a_colh) * 2;
                LDSM_X4T(bf[ntp], bd);
            }
#pragma unroll
            for (int mt = 0; mt < 4; mt++)
#pragma unroll
                for (int ntp = 0; ntp < 4; ntp++) {
                    mma_f16(acc[mt][2 * ntp], af[mt], &bf[ntp][0]);
                    mma_f16(acc[mt][2 * ntp + 1], af[mt], &bf[ntp][2]);
                }
        }
        __syncthreads();
    }

#pragma unroll
    for (int mt = 0; mt < 4; mt++) {
        const int row = m0 + wm * 64 + mt * 16 + lr;
#pragma unroll
        for (int nt = 0; nt < 8; nt++) {
            const int col = n0 + wn * 64 + nt * 8 + kc * 2;
            if (half_out) {
                __half* Ch = (__half*)Cout;
                *(__half2*)&Ch[(size_t)row * N + col] =
                    __floats2half2_rn(acc[mt][nt][0], acc[mt][nt][1]);
                *(__half2*)&Ch[(size_t)(row + 8) * N + col] =
                    __floats2half2_rn(acc[mt][nt][2], acc[mt][nt][3]);
            } else {
                float* Cf = (float*)Cout;
                float b0 = bias[col], b1 = bias[col + 1];
                *(float2*)&Cf[(size_t)row * N + col] =
                    make_float2(acc[mt][nt][0] + b0, acc[mt][nt][1] + b1);
                *(float2*)&Cf[(size_t)(row + 8) * N + col] =
                    make_float2(acc[mt][nt][2] + b0, acc[mt][nt][3] + b1);
            }
        }
    }
}

// ---------------------------------------------------------------------------
// Causal flash attention, fp16 mma + ldmatrix, log2-domain softmax.
// NEW: PV A-fragments built DIRECTLY from the S accumulators (fragment-layout
// identity: accum n-tiles 2kk,2kk+1 == A-frag of PV k-step kk). No P smem,
// no P ldmatrix, no __syncwarp. Smem drops to 55.3 KB.
// ---------------------------------------------------------------------------
#define AQ_PITCH 72
#define AT_QS_B 0
#define AT_K_B  18432       // +9216 per buffer
#define AT_V_B  36864       // +9216 per buffer
#define ATH_SMEM_BYTES 55296

__global__ __launch_bounds__(256) void attn_h(const __half* __restrict__ qkv,
                                              __half* __restrict__ out) {
    extern __shared__ char smc[];
    const uint32_t sbase = smem_to_u32(smc);

    const int tid = threadIdx.x;
    const int wid = tid >> 5, lane = tid & 31;
    const int lr = lane >> 2, kc = lane & 3;
    const int qt = gridDim.x - 1 - blockIdx.x;   // long blocks first
    const int b = blockIdx.y >> 4;
    const int h = blockIdx.y & 15;
    const int row0 = wid * 16 + lr;
    const int row1 = row0 + 8;

    const __half* base = qkv + (size_t)b * T_SEQ * (3 * NEMB) + h * HD;

    auto load_kv = [&](int kt, int buf) {
        const uint32_t kb = sbase + AT_K_B + buf * 9216;
        const uint32_t vb = sbase + AT_V_B + buf * 9216;
        const __half* kp0 = base + NEMB + (size_t)(kt * 64) * (3 * NEMB);
#pragma unroll
        for (int i = 0; i < 2; i++) {
            int id = tid + i * 256;
            int r = id >> 3, cch = id & 7;
            const __half* g = kp0 + (size_t)r * (3 * NEMB) + cch * 8;
            CP_ASYNC16(kb + (uint32_t)(r * AQ_PITCH + cch * 8) * 2, g);
            CP_ASYNC16(vb + (uint32_t)(r * AQ_PITCH + cch * 8) * 2, g + NEMB);
        }
        CP_COMMIT();
    };

    load_kv(0, 0);
    {
        const uint32_t qb = sbase + AT_QS_B;
        const __half* qp0 = base + (size_t)(qt * 128) * (3 * NEMB);
#pragma unroll
        for (int i = 0; i < 4; i++) {
            int id = tid + i * 256;
            int r = id >> 3, cch = id & 7;
            CP_ASYNC16(qb + (uint32_t)(r * AQ_PITCH + cch * 8) * 2,
                       qp0 + (size_t)r * (3 * NEMB) + cch * 8);
        }
        CP_COMMIT();
    }

    float m0 = -1e30f, m1 = -1e30f, l0 = 0.f, l1 = 0.f;
    float O[8][4];
#pragma unroll
    for (int nt = 0; nt < 8; nt++)
#pragma unroll
        for (int r = 0; r < 4; r++) O[nt][r] = 0.f;

    const int a_row = (lane & 15);
    const int a_colh = (lane >> 4) * 8;
    const int s_nrow = (lane >> 4) * 8 + (lane & 7);
    const int s_koff = ((lane >> 3) & 1) * 8;

    const int NT = 2 * qt + 2;
    for (int kt = 0; kt < NT; kt++) {
        const int buf = kt & 1;
        CP_WAIT0();
        __syncthreads();
        if (kt + 1 < NT) load_kv(kt + 1, buf ^ 1);

        const uint32_t kbuf = sbase + AT_K_B + buf * 9216;
        const uint32_t vbuf = sbase + AT_V_B + buf * 9216;
        const uint32_t qb = sbase + AT_QS_B;

        // ---- S = Q K^T (log2 domain)
        float s[8][4];
#pragma unroll
        for (int nt = 0; nt < 8; nt++)
#pragma unroll
            for (int r = 0; r < 4; r++) s[nt][r] = 0.f;

#pragma unroll
        for (int kk = 0; kk < 4; kk++) {
            uint32_t af[4], bf[4][4];
            LDSM_X4(af, qb + (uint32_t)((wid * 16 + a_row) * AQ_PITCH
                                        + kk * 16 + a_colh) * 2);
#pragma unroll
            for (int np = 0; np < 4; np++) {
                LDSM_X4(bf[np], kbuf + (uint32_t)((np * 16 + s_nrow) * AQ_PITCH
                                                  + kk * 16 + s_koff) * 2);
            }
#pragma unroll
            for (int np = 0; np < 4; np++) {
                mma_f16(s[2 * np], af, &bf[np][0]);
                mma_f16(s[2 * np + 1], af, &bf[np][2]);
            }
        }

        if (kt >= 2 * qt) {                  // causal mask (diagonal region)
            const int grow0 = qt * 128 + row0;
            const int grow1 = grow0 + 8;
#pragma unroll
            for (int nt = 0; nt < 8; nt++) {
                int gc = kt * 64 + nt * 8 + kc * 2;
                if (gc > grow0)     s[nt][0] = -1e30f;
                if (gc + 1 > grow0) s[nt][1] = -1e30f;
                if (gc > grow1)     s[nt][2] = -1e30f;
                if (gc + 1 > grow1) s[nt][3] = -1e30f;
            }
        }

        // ---- row max (quad reduce)
        float pm0 = -1e30f, pm1 = -1e30f;
#pragma unroll
        for (int nt = 0; nt < 8; nt++) {
            pm0 = fmaxf(pm0, fmaxf(s[nt][0], s[nt][1]));
            pm1 = fmaxf(pm1, fmaxf(s[nt][2], s[nt][3]));
        }
        pm0 = fmaxf(pm0, __shfl_xor_sync(0xffffffffu, pm0, 1));
        pm0 = fmaxf(pm0, __shfl_xor_sync(0xffffffffu, pm0, 2));
        pm1 = fmaxf(pm1, __shfl_xor_sync(0xffffffffu, pm1, 1));
        pm1 = fmaxf(pm1, __shfl_xor_sync(0xffffffffu, pm1, 2));

        float mn0 = fmaxf(m0, pm0), mn1 = fmaxf(m1, pm1);
        float al0 = exp2_fast(m0 - mn0), al1 = exp2_fast(m1 - mn1);
        m0 = mn0; m1 = mn1;

        // ---- exps with partial sums
        float rsa0 = 0.f, rsb0 = 0.f, rsa1 = 0.f, rsb1 = 0.f;
#pragma unroll
        for (int nt = 0; nt < 8; nt++) {
            s[nt][0] = exp2_fast(s[nt][0] - mn0); rsa0 += s[nt][0];
            s[nt][1] = exp2_fast(s[nt][1] - mn0); rsb0 += s[nt][1];
            s[nt][2] = exp2_fast(s[nt][2] - mn1); rsa1 += s[nt][2];
            s[nt][3] = exp2_fast(s[nt][3] - mn1); rsb1 += s[nt][3];
        }

        // ---- O rescale + PV MMAs (A-fragments direct from s; no smem)
#pragma unroll
        for (int nt = 0; nt < 8; nt++) {
            O[nt][0] *= al0; O[nt][1] *= al0;
            O[nt][2] *= al1; O[nt][3] *= al1;
        }

#pragma unroll
        for (int kk = 0; kk < 4; kk++) {
            uint32_t af[4], bf[4][4];
            af[0] = packh2(s[2 * kk][0],     s[2 * kk][1]);
            af[1] = packh2(s[2 * kk][2],     s[2 * kk][3]);
            af[2] = packh2(s[2 * kk + 1][0], s[2 * kk + 1][1]);
            af[3] = packh2(s[2 * kk + 1][2], s[2 * kk + 1][3]);
#pragma unroll
            for (int np = 0; np < 4; np++) {
                LDSM_X4T(bf[np], vbuf + (uint32_t)((kk * 16 + a_row) * AQ_PITCH
                                                   + np * 16 + a_colh) * 2);
            }
#pragma unroll
            for (int np = 0; np < 4; np++) {
                mma_f16(O[2 * np], af, &bf[np][0]);
                mma_f16(O[2 * np + 1], af, &bf[np][2]);
            }
        }

        // ---- sum reduce + l update LAST (shfl hides under HMMAs)
        float rs0 = rsa0 + rsb0, rs1 = rsa1 + rsb1;
        rs0 += __shfl_xor_sync(0xffffffffu, rs0, 1);
        rs0 += __shfl_xor_sync(0xffffffffu, rs0, 2);
        rs1 += __shfl_xor_sync(0xffffffffu, rs1, 1);
        rs1 += __shfl_xor_sync(0xffffffffu, rs1, 2);
        l0 = l0 * al0 + rs0;
        l1 = l1 * al1 + rs1;
    }

    // Epilogue
    const float inv0 = 1.0f / l0, inv1 = 1.0f / l1;
    const size_t rg0 = (size_t)b * T_SEQ + qt * 128 + row0;
#pragma unroll
    for (int nt = 0; nt < 8; nt++) {
        int col = h * HD + nt * 8 + kc * 2;
        *(__half2*)&out[rg0 * NEMB + col] =
            __floats2half2_rn(O[nt][0] * inv0, O[nt][1] * inv0);
        *(__half2*)&out[(rg0 + 8) * NEMB + col] =
            __floats2half2_rn(O[nt][2] * inv1, O[nt][3] * inv1);
    }
}

// ---------------------------------------------------------------------------
// kernel_launch
// ---------------------------------------------------------------------------
extern "C" void kernel_launch(void* const* d_in, const int* in_sizes, int n_in,
                              void* d_out, int out_size) {
    const float* x     = (const float*)d_in[0];
    const float* w_qkv = (const float*)d_in[1];
    const float* w_out = (const float*)d_in[2];
    const float* b_out = (const float*)d_in[3];
    float* out = (float*)d_out;

    __half *xh, *wqkvh, *wouth, *qkvh, *attnh;
    cudaGetSymbolAddress((void**)&xh, g_xh);
    cudaGetSymbolAddress((void**)&wqkvh, g_wqkvh);
    cudaGetSymbolAddress((void**)&wouth, g_wouth);
    cudaGetSymbolAddress((void**)&qkvh, g_qkvh);
    cudaGetSymbolAddress((void**)&attnh, g_attnh);

    cudaFuncSetAttribute(hgemm, cudaFuncAttributeMaxDynamicSharedMemorySize, HG_SMEM_BYTES);
    cudaFuncSetAttribute(attn_h, cudaFuncAttributeMaxDynamicSharedMemorySize, ATH_SMEM_BYTES);

    const int M = BATCH * T_SEQ;    // 8192

    f2h<<<512, 256>>>(x, xh, M * NEMB);
    f2h_wqkv<<<512, 256>>>(w_qkv, wqkvh, NEMB * 3 * NEMB);
    f2h<<<256, 256>>>(w_out, wouth, NEMB * NEMB);

    hgemm<<<dim3(3 * NEMB / 128, M / 128), 128, HG_SMEM_BYTES>>>(
        xh, wqkvh, nullptr, qkvh, M, 3 * NEMB, NEMB, 1);

    attn_h<<<dim3(T_SEQ / 128, BATCH * NHEADS), 256, ATH_SMEM_BYTES>>>(qkvh, attnh);

    hgemm<<<dim3(NEMB / 128, M / 128), 128, HG_SMEM_BYTES>>>(
        attnh, wouth, b_out, out, M, NEMB, NEMB, 0);
}